// round 5
// baseline (speedup 1.0000x reference)
#include <cuda_runtime.h>

#define N_NODES  100000
#define N_EDGES  1600000
#define N_GRAPHS 512
#define F_IN     256
#define HID      64
#define NB_SCAN  ((N_NODES + 255) / 256)   // 391 scan blocks

// ---------------- scratch (static device globals; no runtime alloc) ----------------
__device__ float2 g_h1[(size_t)N_NODES * 32];   // x @ W1, as 32 float2 per node
__device__ int    g_indeg[N_NODES];
__device__ float  g_dinv[N_NODES];
__device__ int    g_off[N_NODES + 1];
__device__ int    g_cursor[N_NODES];
__device__ int    g_bsum[NB_SCAN];
__device__ int2   g_edge[N_EDGES];              // (src, norm-as-bits), bucketed by dst
__device__ float2 g_msg2[N_NODES];              // relu(agg1) @ W2
__device__ float2 g_agg2[N_NODES];              // layer-2 output per node

// ---------------- K0: zero in-degree histogram ----------------
__global__ void k_init(void) {
    int i = blockIdx.x * blockDim.x + threadIdx.x;
    if (i < N_NODES) g_indeg[i] = 0;
}

// ---------------- K1: in-degree histogram over dst (int32 edge index!) ----------------
__global__ void k_hist(const int* __restrict__ ei) {
    int e = blockIdx.x * blockDim.x + threadIdx.x;
    if (e < N_EDGES) atomicAdd(&g_indeg[ei[N_EDGES + e]], 1);
}

// ---------------- K2: dinv = rsqrt(indeg + 1)  (self loop) ----------------
__global__ void k_dinv(void) {
    int i = blockIdx.x * blockDim.x + threadIdx.x;
    if (i < N_NODES) g_dinv[i] = rsqrtf((float)(g_indeg[i] + 1));
}

// ---------------- scan helpers ----------------
__device__ __forceinline__ int warp_incl_scan(int v) {
#pragma unroll
    for (int o = 1; o < 32; o <<= 1) {
        int n = __shfl_up_sync(0xffffffffu, v, o);
        if ((threadIdx.x & 31) >= o) v += n;
    }
    return v;
}

// K3a: per-block exclusive scan of indeg -> g_off (block-local); block totals -> g_bsum
__global__ void k_scan1(void) {
    __shared__ int wsum[8];
    __shared__ int woff[8];
    int i = blockIdx.x * 256 + threadIdx.x;
    int v = (i < N_NODES) ? g_indeg[i] : 0;
    int incl = warp_incl_scan(v);
    int lane = threadIdx.x & 31, wid = threadIdx.x >> 5;
    if (lane == 31) wsum[wid] = incl;
    __syncthreads();
    if (threadIdx.x == 0) {
        int r = 0;
#pragma unroll
        for (int w = 0; w < 8; ++w) { woff[w] = r; r += wsum[w]; }
        g_bsum[blockIdx.x] = r;
    }
    __syncthreads();
    if (i < N_NODES) g_off[i] = incl - v + woff[wid];
}

// K3b: single-block exclusive scan of the 391 block sums (in place)
__global__ void k_scan2(void) {
    __shared__ int s[512];
    int t = threadIdx.x;
    int orig = (t < NB_SCAN) ? g_bsum[t] : 0;
    s[t] = orig;
    __syncthreads();
    for (int o = 1; o < 512; o <<= 1) {
        int v = (t >= o) ? s[t - o] : 0;
        __syncthreads();
        s[t] += v;
        __syncthreads();
    }
    if (t < NB_SCAN) g_bsum[t] = s[t] - orig;   // exclusive
}

// K3c: add block offsets; init cursor; close off[]
__global__ void k_scan3(void) {
    int i = blockIdx.x * 256 + threadIdx.x;
    if (i < N_NODES) {
        int o = g_off[i] + g_bsum[blockIdx.x];
        g_off[i] = o;
        g_cursor[i] = o;
    }
    if (i == 0) g_off[N_NODES] = N_EDGES;
}

// ---------------- K4: scatter edges into dst buckets with precomputed norm ---------
__global__ void k_scatter(const int* __restrict__ ei) {
    int e = blockIdx.x * blockDim.x + threadIdx.x;
    if (e >= N_EDGES) return;
    int s = ei[e];
    int d = ei[N_EDGES + e];
    float norm = g_dinv[s] * g_dinv[d];
    int pos = atomicAdd(&g_cursor[d], 1);
    g_edge[pos] = make_int2(s, __float_as_int(norm));
}

// ---------------- K5: GEMM1  h1 = x @ W1  (static 32KB smem, 2 column halves) ------
__global__ void __launch_bounds__(256) k_gemm1(const float* __restrict__ x,
                                               const float* __restrict__ W1) {
    __shared__ float4 Ws4[F_IN * 8];   // 32KB: 32 columns of W1
    int node = blockIdx.x * 256 + threadIdx.x;

#pragma unroll
    for (int half = 0; half < 2; ++half) {
        const int c0 = half * 32;
        __syncthreads();   // protect previous half's Ws4 use
        for (int i = threadIdx.x; i < F_IN * 8; i += 256) {
            int k = i >> 3, jj = i & 7;
            const float* wsrc = W1 + k * HID + c0 + jj * 4;
            Ws4[i] = make_float4(wsrc[0], wsrc[1], wsrc[2], wsrc[3]);
        }
        __syncthreads();

        if (node < N_NODES) {
            float acc[32];
#pragma unroll
            for (int j = 0; j < 32; ++j) acc[j] = 0.0f;

            const float4* xrow = reinterpret_cast<const float4*>(x + (size_t)node * F_IN);
#pragma unroll 4
            for (int k4 = 0; k4 < F_IN / 4; ++k4) {
                float4 xv = xrow[k4];
                float xa[4] = {xv.x, xv.y, xv.z, xv.w};
#pragma unroll
                for (int kk = 0; kk < 4; ++kk) {
                    const float xs = xa[kk];
                    const float4* wr = Ws4 + (k4 * 4 + kk) * 8;
#pragma unroll
                    for (int jj = 0; jj < 8; ++jj) {
                        float4 w = wr[jj];
                        acc[jj * 4 + 0] = fmaf(xs, w.x, acc[jj * 4 + 0]);
                        acc[jj * 4 + 1] = fmaf(xs, w.y, acc[jj * 4 + 1]);
                        acc[jj * 4 + 2] = fmaf(xs, w.z, acc[jj * 4 + 2]);
                        acc[jj * 4 + 3] = fmaf(xs, w.w, acc[jj * 4 + 3]);
                    }
                }
            }
#pragma unroll
            for (int i = 0; i < 16; ++i)
                g_h1[(size_t)node * 32 + half * 16 + i] = make_float2(acc[2 * i], acc[2 * i + 1]);
        }
    }
}

// ---------------- K6: fused gather1 + bias + relu + layer2 GEMV ----------------
// One warp per node; lane owns columns [2*lane, 2*lane+1].
__global__ void __launch_bounds__(256) k_gather1(const float* __restrict__ b1,
                                                 const float* __restrict__ W2) {
    __shared__ float W2s[HID * 2];
    if (threadIdx.x < HID * 2) W2s[threadIdx.x] = W2[threadIdx.x];
    __syncthreads();

    int node = blockIdx.x * 8 + (threadIdx.x >> 5);
    if (node >= N_NODES) return;
    int lane = threadIdx.x & 31;

    float dn = g_dinv[node];

    // self loop: dinv[n]^2 * h1[n]
    float2 hv = g_h1[(size_t)node * 32 + lane];
    float d2 = dn * dn;
    float2 acc = make_float2(hv.x * d2, hv.y * d2);

    int beg = g_off[node], end = g_off[node + 1];
    for (int e = beg; e < end; ++e) {
        int2 en = g_edge[e];                           // warp-uniform broadcast
        float norm = __int_as_float(en.y);
        float2 v = g_h1[(size_t)en.x * 32 + lane];     // coalesced 256B row
        acc.x = fmaf(v.x, norm, acc.x);
        acc.y = fmaf(v.y, norm, acc.y);
    }

    float rx = fmaxf(acc.x + b1[2 * lane + 0], 0.0f);
    float ry = fmaxf(acc.y + b1[2 * lane + 1], 0.0f);

    // layer-2 GEMV partials: msg2[n] = relu_row . W2 (W2 is [HID][2])
    float a0 = rx * W2s[4 * lane + 0] + ry * W2s[4 * lane + 2];
    float a1 = rx * W2s[4 * lane + 1] + ry * W2s[4 * lane + 3];
#pragma unroll
    for (int o = 16; o > 0; o >>= 1) {
        a0 += __shfl_down_sync(0xffffffffu, a0, o);
        a1 += __shfl_down_sync(0xffffffffu, a1, o);
    }
    if (lane == 0) g_msg2[node] = make_float2(a0, a1);
}

// ---------------- K7: gather2 (layer-2 aggregation, per node) ----------------
__global__ void k_gather2(const float* __restrict__ b2) {
    int i = blockIdx.x * blockDim.x + threadIdx.x;
    if (i >= N_NODES) return;
    float dn = g_dinv[i];
    float2 m = g_msg2[i];
    float d2 = dn * dn;
    float ax = b2[0] + m.x * d2;
    float ay = b2[1] + m.y * d2;
    int beg = g_off[i], end = g_off[i + 1];
    for (int e = beg; e < end; ++e) {
        int2 en = g_edge[e];
        float norm = __int_as_float(en.y);
        float2 v = g_msg2[en.x];
        ax = fmaf(v.x, norm, ax);
        ay = fmaf(v.y, norm, ay);
    }
    g_agg2[i] = make_float2(ax, ay);
}

// ---------------- K8: mean-pool, one block per graph (batch sorted int32; no atomics)
__device__ __forceinline__ int lower_bound_i(const int* __restrict__ a, int key) {
    int lo = 0, hi = N_NODES;
    while (lo < hi) {
        int mid = (lo + hi) >> 1;
        if (a[mid] < key) lo = mid + 1; else hi = mid;
    }
    return lo;
}

__global__ void __launch_bounds__(256) k_pool(const int* __restrict__ batch,
                                              float* __restrict__ out) {
    __shared__ float sx[256], sy[256];
    int g = blockIdx.x;
    int lo = lower_bound_i(batch, g);
    int hi = lower_bound_i(batch, g + 1);
    float ax = 0.0f, ay = 0.0f;
    for (int i = lo + threadIdx.x; i < hi; i += 256) {
        float2 v = g_agg2[i];
        ax += v.x;
        ay += v.y;
    }
    sx[threadIdx.x] = ax;
    sy[threadIdx.x] = ay;
    __syncthreads();
    for (int o = 128; o > 0; o >>= 1) {
        if (threadIdx.x < o) {
            sx[threadIdx.x] += sx[threadIdx.x + o];
            sy[threadIdx.x] += sy[threadIdx.x + o];
        }
        __syncthreads();
    }
    if (threadIdx.x == 0) {
        float c = fmaxf((float)(hi - lo), 1.0f);
        out[g * 2 + 0] = sx[0] / c;
        out[g * 2 + 1] = sy[0] / c;
    }
}

// ---------------- launch ----------------
extern "C" void kernel_launch(void* const* d_in, const int* in_sizes, int n_in,
                              void* d_out, int out_size) {
    const float* x     = (const float*)d_in[0];
    const int*   ei    = (const int*)d_in[1];    // int32 (JAX x64 disabled)
    const int*   batch = (const int*)d_in[2];    // int32
    const float* W1    = (const float*)d_in[3];
    const float* b1    = (const float*)d_in[4];
    const float* W2    = (const float*)d_in[5];
    const float* b2    = (const float*)d_in[6];
    float*       out   = (float*)d_out;

    k_init<<<(N_NODES + 255) / 256, 256>>>();
    k_hist<<<(N_EDGES + 255) / 256, 256>>>(ei);
    k_dinv<<<(N_NODES + 255) / 256, 256>>>();
    k_scan1<<<NB_SCAN, 256>>>();
    k_scan2<<<1, 512>>>();
    k_scan3<<<NB_SCAN, 256>>>();
    k_scatter<<<(N_EDGES + 255) / 256, 256>>>(ei);
    k_gemm1<<<(N_NODES + 255) / 256, 256>>>(x, W1);
    k_gather1<<<(N_NODES + 7) / 8, 256>>>(b1, W2);
    k_gather2<<<(N_NODES + 255) / 256, 256>>>(b2);
    k_pool<<<N_GRAPHS, 256>>>(batch, out);
}

// round 6
// speedup vs baseline: 1.1364x; 1.1364x over previous
#include <cuda_runtime.h>

#define N_NODES  100000
#define N_EDGES  1600000
#define N_GRAPHS 512
#define F_IN     256
#define HID      64
#define NB_SCAN  ((N_NODES + 255) / 256)   // 391 scan blocks

typedef unsigned long long ull;

// ---------------- scratch (static device globals; no runtime alloc) ----------------
__device__ float2 g_h1[(size_t)N_NODES * 32];   // x @ W1, as 32 float2 per node
__device__ int    g_indeg[N_NODES];
__device__ float  g_dinv[N_NODES];
__device__ int    g_off[N_NODES + 1];
__device__ int    g_cursor[N_NODES];
__device__ int    g_bsum[NB_SCAN];
__device__ int2   g_edge[N_EDGES];              // (src, norm-as-bits), bucketed by dst
__device__ float2 g_msg2[N_NODES];              // relu(agg1) @ W2

// ---------------- f32x2 helpers ----------------
__device__ __forceinline__ ull pack2(float v) {
    ull r;
    asm("mov.b64 %0, {%1, %1};" : "=l"(r) : "f"(v));
    return r;
}
__device__ __forceinline__ ull fma2(ull a, ull b, ull c) {
    ull d;
    asm("fma.rn.f32x2 %0, %1, %2, %3;" : "=l"(d) : "l"(a), "l"(b), "l"(c));
    return d;
}

// ---------------- K0: zero in-degree histogram ----------------
__global__ void k_init(void) {
    int i = blockIdx.x * blockDim.x + threadIdx.x;
    if (i < N_NODES) g_indeg[i] = 0;
}

// ---------------- K1: in-degree histogram over dst ----------------
__global__ void k_hist(const int* __restrict__ ei) {
    int e = blockIdx.x * blockDim.x + threadIdx.x;
    if (e < N_EDGES) atomicAdd(&g_indeg[ei[N_EDGES + e]], 1);
}

// ---------------- scan helpers ----------------
__device__ __forceinline__ int warp_incl_scan(int v) {
#pragma unroll
    for (int o = 1; o < 32; o <<= 1) {
        int n = __shfl_up_sync(0xffffffffu, v, o);
        if ((threadIdx.x & 31) >= o) v += n;
    }
    return v;
}

// K2a: per-block exclusive scan of indeg + fused dinv = rsqrt(indeg+1)
__global__ void k_scan1(void) {
    __shared__ int wsum[8];
    __shared__ int woff[8];
    int i = blockIdx.x * 256 + threadIdx.x;
    int v = (i < N_NODES) ? g_indeg[i] : 0;
    if (i < N_NODES) g_dinv[i] = rsqrtf((float)(v + 1));
    int incl = warp_incl_scan(v);
    int lane = threadIdx.x & 31, wid = threadIdx.x >> 5;
    if (lane == 31) wsum[wid] = incl;
    __syncthreads();
    if (threadIdx.x == 0) {
        int r = 0;
#pragma unroll
        for (int w = 0; w < 8; ++w) { woff[w] = r; r += wsum[w]; }
        g_bsum[blockIdx.x] = r;
    }
    __syncthreads();
    if (i < N_NODES) g_off[i] = incl - v + woff[wid];
}

// K2b: single-block exclusive scan of the 391 block sums (in place)
__global__ void k_scan2(void) {
    __shared__ int s[512];
    int t = threadIdx.x;
    int orig = (t < NB_SCAN) ? g_bsum[t] : 0;
    s[t] = orig;
    __syncthreads();
    for (int o = 1; o < 512; o <<= 1) {
        int v = (t >= o) ? s[t - o] : 0;
        __syncthreads();
        s[t] += v;
        __syncthreads();
    }
    if (t < NB_SCAN) g_bsum[t] = s[t] - orig;   // exclusive
}

// K2c: add block offsets; init cursor; close off[]
__global__ void k_scan3(void) {
    int i = blockIdx.x * 256 + threadIdx.x;
    if (i < N_NODES) {
        int o = g_off[i] + g_bsum[blockIdx.x];
        g_off[i] = o;
        g_cursor[i] = o;
    }
    if (i == 0) g_off[N_NODES] = N_EDGES;
}

// ---------------- K3: scatter edges into dst buckets with precomputed norm ---------
__global__ void k_scatter(const int* __restrict__ ei) {
    int e = blockIdx.x * blockDim.x + threadIdx.x;
    if (e >= N_EDGES) return;
    int s = ei[e];
    int d = ei[N_EDGES + e];
    float norm = g_dinv[s] * g_dinv[d];
    int pos = atomicAdd(&g_cursor[d], 1);
    g_edge[pos] = make_int2(s, __float_as_int(norm));
}

// ---------------- K4: GEMM1  h1 = x @ W1 ----------------
// f32x2 packed FMA; K split into 2 chunks of 128 (x read ONCE); all 64 output
// columns kept live as 32 packed accumulators. W1 chunk staged in 32KB smem as
// 64-bit column pairs (two adjacent floats of a W1 row == one f32x2 operand).
__global__ void __launch_bounds__(256) k_gemm1(const float* __restrict__ x,
                                               const float* __restrict__ W1) {
    __shared__ ull Wp[128 * 32];   // 32KB: rows k (128), 32 column-pairs each
    int node = blockIdx.x * 256 + threadIdx.x;

    ull acc[32];
#pragma unroll
    for (int j = 0; j < 32; ++j) acc[j] = 0ull;

#pragma unroll
    for (int chunk = 0; chunk < 2; ++chunk) {
        __syncthreads();   // protect previous chunk's Wp
        {
            const ulonglong2* src = reinterpret_cast<const ulonglong2*>(W1) + chunk * 2048;
            ulonglong2* dst = reinterpret_cast<ulonglong2*>(Wp);
            for (int i = threadIdx.x; i < 2048; i += 256) dst[i] = src[i];
        }
        __syncthreads();

        if (node < N_NODES) {
            const float4* xrow =
                reinterpret_cast<const float4*>(x + (size_t)node * F_IN + chunk * 128);
            for (int k4 = 0; k4 < 32; ++k4) {
                float4 xv = xrow[k4];
                float xa[4] = {xv.x, xv.y, xv.z, xv.w};
#pragma unroll
                for (int kk = 0; kk < 4; ++kk) {
                    ull xs2 = pack2(xa[kk]);
                    const ull* wr = Wp + (k4 * 4 + kk) * 32;
#pragma unroll
                    for (int j = 0; j < 32; ++j) acc[j] = fma2(xs2, wr[j], acc[j]);
                }
            }
        }
    }

    if (node < N_NODES) {
        ulonglong2* o = reinterpret_cast<ulonglong2*>(g_h1 + (size_t)node * 32);
#pragma unroll
        for (int j = 0; j < 16; ++j) o[j] = make_ulonglong2(acc[2 * j], acc[2 * j + 1]);
    }
}

// ---------------- K5: fused gather1 + bias + relu + layer2 GEMV ----------------
// One warp per node; lane owns columns [2*lane, 2*lane+1].
__global__ void __launch_bounds__(256) k_gather1(const float* __restrict__ b1,
                                                 const float* __restrict__ W2) {
    __shared__ float W2s[HID * 2];
    if (threadIdx.x < HID * 2) W2s[threadIdx.x] = W2[threadIdx.x];
    __syncthreads();

    int node = blockIdx.x * 8 + (threadIdx.x >> 5);
    if (node >= N_NODES) return;
    int lane = threadIdx.x & 31;

    float dn = g_dinv[node];

    // self loop: dinv[n]^2 * h1[n]
    float2 hv = g_h1[(size_t)node * 32 + lane];
    float d2 = dn * dn;
    float2 acc = make_float2(hv.x * d2, hv.y * d2);

    int beg = g_off[node], end = g_off[node + 1];
    for (int e = beg; e < end; ++e) {
        int2 en = g_edge[e];                           // warp-uniform broadcast
        float norm = __int_as_float(en.y);
        float2 v = g_h1[(size_t)en.x * 32 + lane];     // coalesced 256B row
        acc.x = fmaf(v.x, norm, acc.x);
        acc.y = fmaf(v.y, norm, acc.y);
    }

    float rx = fmaxf(acc.x + b1[2 * lane + 0], 0.0f);
    float ry = fmaxf(acc.y + b1[2 * lane + 1], 0.0f);

    // layer-2 GEMV partials: msg2[n] = relu_row . W2 (W2 is [HID][2])
    float a0 = rx * W2s[4 * lane + 0] + ry * W2s[4 * lane + 2];
    float a1 = rx * W2s[4 * lane + 1] + ry * W2s[4 * lane + 3];
#pragma unroll
    for (int o = 16; o > 0; o >>= 1) {
        a0 += __shfl_down_sync(0xffffffffu, a0, o);
        a1 += __shfl_down_sync(0xffffffffu, a1, o);
    }
    if (lane == 0) g_msg2[node] = make_float2(a0, a1);
}

// ---------------- K6: fused gather2 + mean-pool (one block per graph) ---------------
__device__ __forceinline__ int lower_bound_i(const int* __restrict__ a, int key) {
    int lo = 0, hi = N_NODES;
    while (lo < hi) {
        int mid = (lo + hi) >> 1;
        if (a[mid] < key) lo = mid + 1; else hi = mid;
    }
    return lo;
}

__global__ void __launch_bounds__(256) k_pool(const int* __restrict__ batch,
                                              const float* __restrict__ b2,
                                              float* __restrict__ out) {
    __shared__ float sx[256], sy[256];
    int g = blockIdx.x;
    int lo = lower_bound_i(batch, g);
    int hi = lower_bound_i(batch, g + 1);
    float bx = b2[0], by = b2[1];
    float ax = 0.0f, ay = 0.0f;
    for (int i = lo + threadIdx.x; i < hi; i += 256) {
        float dn = g_dinv[i];
        float2 m = g_msg2[i];
        float d2 = dn * dn;
        float vx = bx + m.x * d2;
        float vy = by + m.y * d2;
        int beg = g_off[i], end = g_off[i + 1];
        for (int e = beg; e < end; ++e) {
            int2 en = g_edge[e];
            float norm = __int_as_float(en.y);
            float2 v = g_msg2[en.x];
            vx = fmaf(v.x, norm, vx);
            vy = fmaf(v.y, norm, vy);
        }
        ax += vx;
        ay += vy;
    }
    sx[threadIdx.x] = ax;
    sy[threadIdx.x] = ay;
    __syncthreads();
    for (int o = 128; o > 0; o >>= 1) {
        if (threadIdx.x < o) {
            sx[threadIdx.x] += sx[threadIdx.x + o];
            sy[threadIdx.x] += sy[threadIdx.x + o];
        }
        __syncthreads();
    }
    if (threadIdx.x == 0) {
        float c = fmaxf((float)(hi - lo), 1.0f);
        out[g * 2 + 0] = sx[0] / c;
        out[g * 2 + 1] = sy[0] / c;
    }
}

// ---------------- launch ----------------
extern "C" void kernel_launch(void* const* d_in, const int* in_sizes, int n_in,
                              void* d_out, int out_size) {
    const float* x     = (const float*)d_in[0];
    const int*   ei    = (const int*)d_in[1];    // int32
    const int*   batch = (const int*)d_in[2];    // int32
    const float* W1    = (const float*)d_in[3];
    const float* b1    = (const float*)d_in[4];
    const float* W2    = (const float*)d_in[5];
    const float* b2    = (const float*)d_in[6];
    float*       out   = (float*)d_out;

    k_init<<<(N_NODES + 255) / 256, 256>>>();
    k_hist<<<(N_EDGES + 255) / 256, 256>>>(ei);
    k_scan1<<<NB_SCAN, 256>>>();
    k_scan2<<<1, 512>>>();
    k_scan3<<<NB_SCAN, 256>>>();
    k_scatter<<<(N_EDGES + 255) / 256, 256>>>(ei);
    k_gemm1<<<(N_NODES + 255) / 256, 256>>>(x, W1);
    k_gather1<<<(N_NODES + 7) / 8, 256>>>(b1, W2);
    k_pool<<<N_GRAPHS, 256>>>(batch, b2, out);
}

// round 7
// speedup vs baseline: 1.2269x; 1.0796x over previous
#include <cuda_runtime.h>

#define N_NODES  100000
#define N_EDGES  1600000
#define N_GRAPHS 512
#define F_IN     256
#define HID      64
#define NB_SCAN  ((N_NODES + 255) / 256)   // 391 scan blocks

typedef unsigned long long ull;

// ---------------- scratch (static device globals; no runtime alloc) ----------------
__device__ float2 g_h1[(size_t)N_NODES * 32];   // x @ W1, as 32 float2 per node
__device__ int    g_indeg[N_NODES];
__device__ float  g_dinv[N_NODES];
__device__ int    g_off[N_NODES + 1];
__device__ int    g_cursor[N_NODES];
__device__ int    g_bsum[NB_SCAN];
__device__ int2   g_edge[N_EDGES];              // (src, norm-as-bits), bucketed by dst
__device__ float2 g_msg2[N_NODES];              // relu(agg1) @ W2

// ---------------- f32x2 helpers ----------------
__device__ __forceinline__ ull pack2(float v) {
    ull r;
    asm("mov.b64 %0, {%1, %1};" : "=l"(r) : "f"(v));
    return r;
}
__device__ __forceinline__ ull fma2(ull a, ull b, ull c) {
    ull d;
    asm("fma.rn.f32x2 %0, %1, %2, %3;" : "=l"(d) : "l"(a), "l"(b), "l"(c));
    return d;
}

// ---------------- K0: zero in-degree histogram ----------------
__global__ void k_init(void) {
    int i = blockIdx.x * blockDim.x + threadIdx.x;
    if (i < N_NODES) g_indeg[i] = 0;
}

// ---------------- K1: in-degree histogram over dst ----------------
__global__ void k_hist(const int* __restrict__ ei) {
    int e = blockIdx.x * blockDim.x + threadIdx.x;
    if (e < N_EDGES) atomicAdd(&g_indeg[ei[N_EDGES + e]], 1);
}

// ---------------- scan helpers ----------------
__device__ __forceinline__ int warp_incl_scan(int v) {
#pragma unroll
    for (int o = 1; o < 32; o <<= 1) {
        int n = __shfl_up_sync(0xffffffffu, v, o);
        if ((threadIdx.x & 31) >= o) v += n;
    }
    return v;
}

// K2a: per-block exclusive scan of indeg + fused dinv = rsqrt(indeg+1)
__global__ void k_scan1(void) {
    __shared__ int wsum[8];
    __shared__ int woff[8];
    int i = blockIdx.x * 256 + threadIdx.x;
    int v = (i < N_NODES) ? g_indeg[i] : 0;
    if (i < N_NODES) g_dinv[i] = rsqrtf((float)(v + 1));
    int incl = warp_incl_scan(v);
    int lane = threadIdx.x & 31, wid = threadIdx.x >> 5;
    if (lane == 31) wsum[wid] = incl;
    __syncthreads();
    if (threadIdx.x == 0) {
        int r = 0;
#pragma unroll
        for (int w = 0; w < 8; ++w) { woff[w] = r; r += wsum[w]; }
        g_bsum[blockIdx.x] = r;
    }
    __syncthreads();
    if (i < N_NODES) g_off[i] = incl - v + woff[wid];
}

// K2b: single-block exclusive scan of the 391 block sums (in place)
__global__ void k_scan2(void) {
    __shared__ int s[512];
    int t = threadIdx.x;
    int orig = (t < NB_SCAN) ? g_bsum[t] : 0;
    s[t] = orig;
    __syncthreads();
    for (int o = 1; o < 512; o <<= 1) {
        int v = (t >= o) ? s[t - o] : 0;
        __syncthreads();
        s[t] += v;
        __syncthreads();
    }
    if (t < NB_SCAN) g_bsum[t] = s[t] - orig;   // exclusive
}

// K2c: add block offsets; init cursor; close off[]
__global__ void k_scan3(void) {
    int i = blockIdx.x * 256 + threadIdx.x;
    if (i < N_NODES) {
        int o = g_off[i] + g_bsum[blockIdx.x];
        g_off[i] = o;
        g_cursor[i] = o;
    }
    if (i == 0) g_off[N_NODES] = N_EDGES;
}

// ---------------- K3: scatter edges into dst buckets with precomputed norm ---------
__global__ void k_scatter(const int* __restrict__ ei) {
    int e = blockIdx.x * blockDim.x + threadIdx.x;
    if (e >= N_EDGES) return;
    int s = ei[e];
    int d = ei[N_EDGES + e];
    float norm = g_dinv[s] * g_dinv[d];
    int pos = atomicAdd(&g_cursor[d], 1);
    g_edge[pos] = make_int2(s, __float_as_int(norm));
}

// ---------------- K4: GEMM1  h1 = x @ W1  (f32x2, K-chunked, x read once) ----------
__global__ void __launch_bounds__(256) k_gemm1(const float* __restrict__ x,
                                               const float* __restrict__ W1) {
    __shared__ ull Wp[128 * 32];   // 32KB: rows k (128), 32 column-pairs each
    int node = blockIdx.x * 256 + threadIdx.x;

    ull acc[32];
#pragma unroll
    for (int j = 0; j < 32; ++j) acc[j] = 0ull;

#pragma unroll
    for (int chunk = 0; chunk < 2; ++chunk) {
        __syncthreads();   // protect previous chunk's Wp
        {
            const ulonglong2* src = reinterpret_cast<const ulonglong2*>(W1) + chunk * 2048;
            ulonglong2* dst = reinterpret_cast<ulonglong2*>(Wp);
            for (int i = threadIdx.x; i < 2048; i += 256) dst[i] = src[i];
        }
        __syncthreads();

        if (node < N_NODES) {
            const float4* xrow =
                reinterpret_cast<const float4*>(x + (size_t)node * F_IN + chunk * 128);
            for (int k4 = 0; k4 < 32; ++k4) {
                float4 xv = xrow[k4];
                float xa[4] = {xv.x, xv.y, xv.z, xv.w};
#pragma unroll
                for (int kk = 0; kk < 4; ++kk) {
                    ull xs2 = pack2(xa[kk]);
                    const ull* wr = Wp + (k4 * 4 + kk) * 32;
#pragma unroll
                    for (int j = 0; j < 32; ++j) acc[j] = fma2(xs2, wr[j], acc[j]);
                }
            }
        }
    }

    if (node < N_NODES) {
        ulonglong2* o = reinterpret_cast<ulonglong2*>(g_h1 + (size_t)node * 32);
#pragma unroll
        for (int j = 0; j < 16; ++j) o[j] = make_ulonglong2(acc[2 * j], acc[2 * j + 1]);
    }
}

// ---------------- K5: fused gather1 + bias + relu + layer2 GEMV ----------------
// One warp per node; lane owns columns [2*lane, 2*lane+1].
__global__ void __launch_bounds__(256) k_gather1(const float* __restrict__ b1,
                                                 const float* __restrict__ W2) {
    __shared__ float W2s[HID * 2];
    if (threadIdx.x < HID * 2) W2s[threadIdx.x] = W2[threadIdx.x];
    __syncthreads();

    int node = blockIdx.x * 8 + (threadIdx.x >> 5);
    if (node >= N_NODES) return;
    int lane = threadIdx.x & 31;

    float dn = g_dinv[node];

    // self loop: dinv[n]^2 * h1[n]
    float2 hv = g_h1[(size_t)node * 32 + lane];
    float d2 = dn * dn;
    float2 acc = make_float2(hv.x * d2, hv.y * d2);

    int beg = g_off[node], end = g_off[node + 1];
    for (int e = beg; e < end; ++e) {
        int2 en = g_edge[e];                           // warp-uniform broadcast
        float norm = __int_as_float(en.y);
        float2 v = g_h1[(size_t)en.x * 32 + lane];     // coalesced 256B row
        acc.x = fmaf(v.x, norm, acc.x);
        acc.y = fmaf(v.y, norm, acc.y);
    }

    float rx = fmaxf(acc.x + b1[2 * lane + 0], 0.0f);
    float ry = fmaxf(acc.y + b1[2 * lane + 1], 0.0f);

    // layer-2 GEMV partials: msg2[n] = relu_row . W2 (W2 is [HID][2])
    float a0 = rx * W2s[4 * lane + 0] + ry * W2s[4 * lane + 2];
    float a1 = rx * W2s[4 * lane + 1] + ry * W2s[4 * lane + 3];
#pragma unroll
    for (int o = 16; o > 0; o >>= 1) {
        a0 += __shfl_down_sync(0xffffffffu, a0, o);
        a1 += __shfl_down_sync(0xffffffffu, a1, o);
    }
    if (lane == 0) g_msg2[node] = make_float2(a0, a1);
}

// ---------------- K6: fused gather2 + mean-pool (one block per graph) ---------------
__device__ __forceinline__ int lower_bound_i(const int* __restrict__ a, int key) {
    int lo = 0, hi = N_NODES;
    while (lo < hi) {
        int mid = (lo + hi) >> 1;
        if (a[mid] < key) lo = mid + 1; else hi = mid;
    }
    return lo;
}

__global__ void __launch_bounds__(256) k_pool(const int* __restrict__ batch,
                                              const float* __restrict__ b2,
                                              float* __restrict__ out) {
    __shared__ float sx[256], sy[256];
    int g = blockIdx.x;
    int lo = lower_bound_i(batch, g);
    int hi = lower_bound_i(batch, g + 1);
    float bx = b2[0], by = b2[1];
    float ax = 0.0f, ay = 0.0f;
    for (int i = lo + threadIdx.x; i < hi; i += 256) {
        float dn = g_dinv[i];
        float2 m = g_msg2[i];
        float d2 = dn * dn;
        float vx = bx + m.x * d2;
        float vy = by + m.y * d2;
        int beg = g_off[i], end = g_off[i + 1];
        for (int e = beg; e < end; ++e) {
            int2 en = g_edge[e];
            float norm = __int_as_float(en.y);
            float2 v = g_msg2[en.x];
            vx = fmaf(v.x, norm, vx);
            vy = fmaf(v.y, norm, vy);
        }
        ax += vx;
        ay += vy;
    }
    sx[threadIdx.x] = ax;
    sy[threadIdx.x] = ay;
    __syncthreads();
    for (int o = 128; o > 0; o >>= 1) {
        if (threadIdx.x < o) {
            sx[threadIdx.x] += sx[threadIdx.x + o];
            sy[threadIdx.x] += sy[threadIdx.x + o];
        }
        __syncthreads();
    }
    if (threadIdx.x == 0) {
        float c = fmaxf((float)(hi - lo), 1.0f);
        out[g * 2 + 0] = sx[0] / c;
        out[g * 2 + 1] = sy[0] / c;
    }
}

// ---------------- launch: fork GEMM1 onto a side stream (graph branch) --------------
extern "C" void kernel_launch(void* const* d_in, const int* in_sizes, int n_in,
                              void* d_out, int out_size) {
    const float* x     = (const float*)d_in[0];
    const int*   ei    = (const int*)d_in[1];    // int32
    const int*   batch = (const int*)d_in[2];    // int32
    const float* W1    = (const float*)d_in[3];
    const float* b1    = (const float*)d_in[4];
    const float* W2    = (const float*)d_in[5];
    const float* b2    = (const float*)d_in[6];
    float*       out   = (float*)d_out;

    cudaStream_t s2;
    cudaEvent_t evFork, evJoin;
    cudaStreamCreateWithFlags(&s2, cudaStreamNonBlocking);
    cudaEventCreateWithFlags(&evFork, cudaEventDisableTiming);
    cudaEventCreateWithFlags(&evJoin, cudaEventDisableTiming);

    // Fork: side stream inherits capture via event dependency.
    cudaEventRecord(evFork, 0);
    cudaStreamWaitEvent(s2, evFork, 0);

    // Branch A (side stream): dense projection, independent of edges.
    k_gemm1<<<(N_NODES + 255) / 256, 256, 0, s2>>>(x, W1);
    cudaEventRecord(evJoin, s2);

    // Branch B (main stream): CSR build chain.
    k_init<<<(N_NODES + 255) / 256, 256>>>();
    k_hist<<<(N_EDGES + 255) / 256, 256>>>(ei);
    k_scan1<<<NB_SCAN, 256>>>();
    k_scan2<<<1, 512>>>();
    k_scan3<<<NB_SCAN, 256>>>();
    k_scatter<<<(N_EDGES + 255) / 256, 256>>>(ei);

    // Join: gather1 needs both h1 and the CSR.
    cudaStreamWaitEvent(0, evJoin, 0);
    k_gather1<<<(N_NODES + 7) / 8, 256>>>(b1, W2);
    k_pool<<<N_GRAPHS, 256>>>(batch, b2, out);

    // Note: stream/events are host-side objects created per call; they are not
    // destroyed here to avoid touching in-flight captured work. Replays of the
    // captured graph never re-execute this host code.
}